// round 14
// baseline (speedup 1.0000x reference)
#include <cuda_runtime.h>
#include <cuda_bf16.h>
#include <math.h>
#include <stdint.h>

// ---------------- problem constants ----------------
#define B_  8
#define T_  4096
#define D_  256
#define M_  (B_ * T_)      // 32768
#define K_  256
#define N_TOT 512

// ---------------- scan chunking ----------------
#define LCH 64
#define NCH (T_ / LCH)          // 64 chunks per batch
#define NBLK ((M_ / LCH) * 4)   // 2048 fused blocks (4 d-quadrants)

// ---------------- scratch (static device allocations) ----------------
__device__ uint4 g_Whi4[(N_TOT * K_) / 8];       // permuted rows (see prep)
__device__ uint4 g_Wlo4[(N_TOT * K_) / 8];
__device__ uint4 g_Ahi4[((size_t)M_ * K_) / 8];  // [m][k] bf16 hi
__device__ uint4 g_Alo4[((size_t)M_ * K_) / 8];  // [m][k] bf16 lo
// decoupled-lookback state: NBLK * 64 channels = 131072 slots
__device__ float    g_SA [NBLK * 64];
__device__ float    g_SHl[NBLK * 64];
__device__ float    g_SHI[NBLK * 64];
__device__ uint32_t g_flag[NBLK * 64];

// ---------------- smem layout ----------------
// stage: Ahi 8K | Alo 8K | Whi 16K | Wlo 16K = 48K; two stages = 96K
#define ST_ALO   8192
#define ST_WHI   16384
#define ST_WLO   32768
#define ST_SIZE  49152
#define SM_BIAS  98304      // 128 floats
#define SM_MK    98816      // 64 floats
#define SM_TOTAL 99072
// epilogue staging (reuses stage space after final sync)
#define SM_XS    0          // xs[64][STG]  (17408 B)
#define SM_FS    20480      // fs[64][STG]
#define SM_SA    40960      // segment A  [8][STG]
#define SM_SH    43520      // segment h  [8][STG]
#define SM_HX    46080      // h0 per channel [64]
#define STG      68

// ---------------- asm helpers (base sm_103 features only) ----------------
__device__ __forceinline__ uint32_t smem_u32(const void* p) {
    uint32_t a;
    asm("{ .reg .u64 t; cvta.to.shared.u64 t, %1; cvt.u32.u64 %0, t; }" : "=r"(a) : "l"(p));
    return a;
}
#define LDSM4(r, addr) asm volatile( \
    "ldmatrix.sync.aligned.m8n8.x4.shared.b16 {%0,%1,%2,%3}, [%4];" \
    : "=r"((r)[0]), "=r"((r)[1]), "=r"((r)[2]), "=r"((r)[3]) : "r"(addr))
#define MMA(d, a, b0v, b1v) asm volatile( \
    "mma.sync.aligned.m16n8k16.row.col.f32.bf16.bf16.f32 " \
    "{%0,%1,%2,%3}, {%4,%5,%6,%7}, {%8,%9}, {%0,%1,%2,%3};" \
    : "+f"((d)[0]), "+f"((d)[1]), "+f"((d)[2]), "+f"((d)[3]) \
    : "r"((a)[0]), "r"((a)[1]), "r"((a)[2]), "r"((a)[3]), "r"(b0v), "r"(b1v))
__device__ __forceinline__ void cp_async16(uint32_t dst, const void* src) {
    asm volatile("cp.async.cg.shared.global [%0], [%1], 16;" :: "r"(dst), "l"(src));
}
#define CP_COMMIT() asm volatile("cp.async.commit_group;" ::: "memory")
__device__ __forceinline__ void st_release_u32(uint32_t* p, uint32_t v) {
    asm volatile("st.global.release.gpu.b32 [%0], %1;" :: "l"(p), "r"(v) : "memory");
}
__device__ __forceinline__ uint32_t ld_acquire_u32(const uint32_t* p) {
    uint32_t v;
    asm volatile("ld.global.acquire.gpu.b32 %0, [%1];" : "=r"(v) : "l"(p) : "memory");
    return v;
}

// ---------------------------------------------------------------------------
// prep: A fp32 -> hi/lo bf16 (all threads); W split + flag zero (first slice).
// W permuted rows: p = qb*128 + branch*64 + (d & 63), qb = d >> 6.
// ---------------------------------------------------------------------------
__global__ void prep_kernel(const float4* __restrict__ A4,
                            const float* __restrict__ W_in,
                            const float* __restrict__ W_f)
{
    int i = blockIdx.x * blockDim.x + threadIdx.x;   // 0 .. 2,097,151
    float4 a = A4[i];
    __nv_bfloat16 h0 = __float2bfloat16_rn(a.x), h1 = __float2bfloat16_rn(a.y),
                  h2 = __float2bfloat16_rn(a.z), h3 = __float2bfloat16_rn(a.w);
    __nv_bfloat162 hp0 = {h0, h1}, hp1 = {h2, h3};
    __nv_bfloat162 lp0 = __floats2bfloat162_rn(a.x - __bfloat162float(h0),
                                               a.y - __bfloat162float(h1));
    __nv_bfloat162 lp1 = __floats2bfloat162_rn(a.z - __bfloat162float(h2),
                                               a.w - __bfloat162float(h3));
    ((uint2*)g_Ahi4)[i] = make_uint2(*(uint32_t*)&hp0, *(uint32_t*)&hp1);
    ((uint2*)g_Alo4)[i] = make_uint2(*(uint32_t*)&lp0, *(uint32_t*)&lp1);

    if (i < NBLK * 64) {             // == N_TOT*K_ == 131072
        g_flag[i] = 0u;
        int p = i >> 8, k = i & 255;
        int qb = p >> 7;
        int rem = p & 127;
        int branch = rem >> 6;
        int d = qb * 64 + (rem & 63);
        float v = branch ? W_f[d * K_ + k] : W_in[d * K_ + k];
        __nv_bfloat16 hi = __float2bfloat16_rn(v);
        ((__nv_bfloat16*)g_Whi4)[i] = hi;
        ((__nv_bfloat16*)g_Wlo4)[i] = __float2bfloat16_rn(v - __bfloat162float(hi));
    }
}

// ---------------------------------------------------------------------------
// Fused: split-bf16 mma GEMM + activations + segmented scan + batched
// decoupled lookback + output.  grid = 2048, 512 threads, 2 CTA/SM.
// Block tile: 64 m x 128 n  (n_local 0..63 = X cols, 64..127 = F cols).
// ---------------------------------------------------------------------------
__global__ __launch_bounds__(512, 2)
void fused_kernel(const float* __restrict__ b_in,
                  const float* __restrict__ b_f,
                  const float* __restrict__ mask,
                  float* __restrict__ out)
{
    extern __shared__ __align__(16) char smem[];
    const uint32_t sb = smem_u32(smem);
    const int tid = threadIdx.x;
    const int w   = tid >> 5, l = tid & 31;
    const int wm  = w >> 2;           // 0..3, 16-row strip
    const int wn  = w & 3;            // 0..3, 32-col strip
    const int bid = blockIdx.x;
    const int m0  = (bid >> 2) * 64;
    const int qb  = bid & 3;

    auto issueStage = [&](int kc, int buf) {
        const uint32_t base = sb + (buf ? ST_SIZE : 0);
#pragma unroll
        for (int it = 0; it < 2; it++) {
            int v   = it * 512 + tid;
            int arr = v >> 9;
            int u   = v & 511;
            int row = u >> 3, c8 = u & 7;
            uint32_t dst = base + (arr ? ST_ALO : 0)
                         + row * 128 + ((c8 ^ (row & 7)) << 4);
            const uint4* src = (arr ? g_Alo4 : g_Ahi4)
                             + ((size_t)(m0 + row) * 32 + kc * 8 + c8);
            cp_async16(dst, src);
        }
#pragma unroll
        for (int it = 0; it < 4; it++) {
            int v   = it * 512 + tid;
            int arr = v >> 10;
            int u   = v & 1023;
            int n   = u >> 3, k8 = u & 7;
            uint32_t dst = base + (arr ? ST_WLO : ST_WHI)
                         + n * 128 + ((k8 ^ (n & 7)) << 4);
            const uint4* src = (arr ? g_Wlo4 : g_Whi4)
                             + ((size_t)(qb * 128 + n) * 32 + kc * 8 + k8);
            cp_async16(dst, src);
        }
        CP_COMMIT();
    };

    issueStage(0, 0);
    issueStage(1, 1);

    if (tid < 128) {
        int branch = tid >> 6;
        int d = qb * 64 + (tid & 63);
        *(float*)(smem + SM_BIAS + tid * 4) = branch ? b_f[d] : b_in[d];
    }
    if (tid < 64) *(float*)(smem + SM_MK + tid * 4) = mask[m0 + tid] * 10000.0f;

    float acc[4][4];
#pragma unroll
    for (int a2 = 0; a2 < 4; a2++)
#pragma unroll
        for (int a3 = 0; a3 < 4; a3++) acc[a2][a3] = 0.0f;

    const int g = l >> 3;

    for (int kc = 0; kc < 4; kc++) {
        const int buf = kc & 1;
        if (kc < 3) asm volatile("cp.async.wait_group 1;" ::: "memory");
        else        asm volatile("cp.async.wait_group 0;" ::: "memory");
        __syncthreads();
        const uint32_t base = sb + (buf ? ST_SIZE : 0);

#pragma unroll
        for (int ks = 0; ks < 4; ks++) {
            uint32_t ah[4], al[4];
            {
                int r = wm * 16 + ((g & 1) << 3) + (l & 7);
                int c = ks * 16 + ((g & 2) << 2);
                uint32_t off = r * 128 + ((((c >> 3) ^ (r & 7))) << 4);
                LDSM4(ah, base + off);
                LDSM4(al, base + ST_ALO + off);
            }
            uint32_t bh[2][4], bl[2][4];
#pragma unroll
            for (int ng = 0; ng < 2; ng++) {
                int n  = wn * 32 + ng * 16 + ((g & 2) << 2) + (l & 7);
                int kk = ks * 16 + ((g & 1) << 3);
                uint32_t woff = n * 128 + ((((kk >> 3) ^ (n & 7))) << 4);
                LDSM4(bh[ng], base + ST_WHI + woff);
                LDSM4(bl[ng], base + ST_WLO + woff);
            }
#pragma unroll
            for (int ng = 0; ng < 2; ng++) {
                MMA(acc[ng * 2 + 0], ah, bh[ng][0], bh[ng][1]);
                MMA(acc[ng * 2 + 1], ah, bh[ng][2], bh[ng][3]);
            }
#pragma unroll
            for (int ng = 0; ng < 2; ng++) {
                MMA(acc[ng * 2 + 0], al, bh[ng][0], bh[ng][1]);
                MMA(acc[ng * 2 + 1], al, bh[ng][2], bh[ng][3]);
            }
#pragma unroll
            for (int ng = 0; ng < 2; ng++) {
                MMA(acc[ng * 2 + 0], ah, bl[ng][0], bl[ng][1]);
                MMA(acc[ng * 2 + 1], ah, bl[ng][2], bl[ng][3]);
            }
        }
        __syncthreads();
        if (kc < 2) issueStage(kc + 2, buf);
    }

    // -------- epilogue: activations -> smem staging --------
    float* xs = (float*)(smem + SM_XS);
    float* fs = (float*)(smem + SM_FS);
    const float* biasS = (const float*)(smem + SM_BIAS);
    const float* mkS   = (const float*)(smem + SM_MK);

#pragma unroll
    for (int nt = 0; nt < 4; nt++) {
        int r0 = wm * 16 + (l >> 2);
        int nl = wn * 32 + nt * 8 + 2 * (l & 3);
        bool isF = (nl >= 64);
        float* stg = isF ? fs : xs;
        int cc = nl & 63;
        float b0 = biasS[nl], b1 = biasS[nl + 1];
#pragma unroll
        for (int h = 0; h < 2; h++) {
            int r = r0 + h * 8;
            float z0 = acc[nt][h * 2 + 0] + b0;
            float z1 = acc[nt][h * 2 + 1] + b1;
            float v0, v1;
            if (isF) {
                float mk = mkS[r];
                z0 += mk; z1 += mk;
                v0 = 1.0f / (1.0f + expf(-z0));
                v1 = 1.0f / (1.0f + expf(-z1));
            } else {
                v0 = tanhf(z0);
                v1 = tanhf(z1);
            }
            stg[r * STG + cc]     = v0;
            stg[r * STG + cc + 1] = v1;
        }
    }
    __syncthreads();

    // -------- segmented scan: thread (j = tid>>6, dl = tid&63), 8 t each ----
    const int j  = tid >> 6;
    const int dl = tid & 63;
    float* sA = (float*)(smem + SM_SA);
    float* sH = (float*)(smem + SM_SH);
    float* hx = (float*)(smem + SM_HX);

    {   // Phase A: segment summary
        float As = 1.0f, hs = 0.0f;
#pragma unroll
        for (int s = 0; s < 8; s++) {
            int t = j * 8 + s;
            float f = fs[t * STG + dl];
            float x = xs[t * STG + dl];
            float om = 1.0f - f;
            hs = fmaf(f, x, om * hs);
            As *= om;
        }
        sA[j * STG + dl] = As;
        sH[j * STG + dl] = hs;
    }
    __syncthreads();

    // Phase B: exclusive prefix over segments < j
    float Ae = 1.0f, he = 0.0f;
    for (int q = 0; q < j; q++) {
        float a  = sA[q * STG + dl];
        float hh = sH[q * STG + dl];
        he = fmaf(a, he, hh);
        Ae *= a;
    }

    // Phase C: batched lookback (threads 0..63)
    if (tid < 64) {
        const int slot = bid * 64 + dl;
        float Af = 1.0f, hf = 0.0f;
#pragma unroll
        for (int q = 0; q < 8; q++) {
            float a  = sA[q * STG + dl];
            float hh = sH[q * STG + dl];
            hf = fmaf(a, hf, hh);
            Af *= a;
        }
        const int c = (bid >> 2) & (NCH - 1);
        float h0 = 0.0f;
        if (c != 0) {
            g_SA [slot] = Af;
            g_SHl[slot] = hf;
            st_release_u32(&g_flag[slot], 1u);
            float mult = 1.0f;
            int dist = 1;
            bool done = false;
            while (!done) {
                int nb8 = c - dist + 1; if (nb8 > 8) nb8 = 8;
                const int pb = slot - dist * 256;
                uint32_t fl[8];
#pragma unroll
                for (int i = 0; i < 8; i++) fl[i] = 0u;
                bool all;
                do {   // batched flag poll: independent acquires, high MLP
                    all = true;
#pragma unroll
                    for (int i = 0; i < 8; i++)
                        if (i < nb8 && fl[i] == 0u) {
                            fl[i] = ld_acquire_u32(&g_flag[pb - i * 256]);
                            if (fl[i] == 0u) all = false;
                        }
                } while (!all);
                float pa[8], ph[8], pi_[8];
#pragma unroll
                for (int i = 0; i < 8; i++)
                    if (i < nb8) {
                        pa[i]  = g_SA [pb - i * 256];
                        ph[i]  = g_SHl[pb - i * 256];
                        pi_[i] = g_SHI[pb - i * 256];
                    }
#pragma unroll
                for (int i = 0; i < 8; i++) {
                    if (i < nb8 && !done) {
                        if (fl[i] == 2u) { h0 = fmaf(mult, pi_[i], h0); done = true; }
                        else             { h0 = fmaf(mult, ph[i], h0); mult *= pa[i]; }
                    }
                }
                if (!done) dist += nb8;
            }
        }
        g_SHI[slot] = fmaf(Af, h0, hf);
        st_release_u32(&g_flag[slot], 2u);
        hx[dl] = h0;
    }
    __syncthreads();

    // Phase D: replay 8 steps from segment entry state, coalesced stores
    {
        float h = fmaf(Ae, hx[dl], he);
        float* op = out + (size_t)(m0 + j * 8) * D_ + qb * 64 + dl;
#pragma unroll
        for (int s = 0; s < 8; s++) {
            int t = j * 8 + s;
            float f = fs[t * STG + dl];
            float x = xs[t * STG + dl];
            h = fmaf(f, x - h, h);
            op[(size_t)s * D_] = h;
        }
    }
}

extern "C" void kernel_launch(void* const* d_in, const int* in_sizes, int n_in,
                              void* d_out, int out_size)
{
    const float* inputs = (const float*)d_in[0];
    const float* mask   = (const float*)d_in[1];
    const float* W_in   = (const float*)d_in[2];
    const float* b_in   = (const float*)d_in[3];
    const float* W_f    = (const float*)d_in[4];
    const float* b_f    = (const float*)d_in[5];
    float* out = (float*)d_out;

    cudaFuncSetAttribute(fused_kernel, cudaFuncAttributeMaxDynamicSharedMemorySize, SM_TOTAL);

    prep_kernel<<<(M_ * K_ / 4) / 256, 256>>>((const float4*)inputs, W_in, W_f);
    fused_kernel<<<NBLK, 512, SM_TOTAL>>>(b_in, b_f, mask, out);
}

// round 15
// speedup vs baseline: 1.0115x; 1.0115x over previous
#include <cuda_runtime.h>
#include <cuda_bf16.h>
#include <math.h>
#include <stdint.h>

// ---------------- problem constants ----------------
#define B_  8
#define T_  4096
#define D_  256
#define M_  (B_ * T_)      // 32768
#define K_  256
#define N_TOT 512

// ---------------- scan chunking ----------------
#define LCH 128
#define NCH (T_ / LCH)          // 32 chunks per batch
#define NBLK ((M_ / LCH) * 2)   // 512 fused blocks (2 d-halves)

// ---------------- scratch (static device allocations) ----------------
__device__ uint4 g_Whi4[(N_TOT * K_) / 8];       // permuted rows (see prep)
__device__ uint4 g_Wlo4[(N_TOT * K_) / 8];
__device__ uint4 g_Ahi4[((size_t)M_ * K_) / 8];  // [m][k] bf16 hi
__device__ uint4 g_Alo4[((size_t)M_ * K_) / 8];  // [m][k] bf16 lo
// decoupled-lookback state: NBLK * 128 channels = 65536 slots
__device__ float    g_SA [NBLK * 128];
__device__ float    g_SHl[NBLK * 128];
__device__ float    g_SHI[NBLK * 128];
__device__ uint32_t g_flag[NBLK * 128];

// ---------------- smem layout ----------------
// stage: Ahi 16K | Alo 16K | Whi 32K | Wlo 32K = 96K; two stages = 192K
#define ST_ALO   16384
#define ST_WHI   32768
#define ST_WLO   65536
#define ST_SIZE  98304
#define SM_BIAS  196608     // 256 floats
#define SM_MK    197632     // 128 floats
#define SM_TOTAL 198144
// epilogue staging (reuses stage space after final sync)
#define SM_XS    0          // xs[128][STG]
#define SM_FS    69632      // fs[128][STG]
#define STG      132

// ---------------- asm helpers (base sm_103 features only) ----------------
__device__ __forceinline__ uint32_t smem_u32(const void* p) {
    uint32_t a;
    asm("{ .reg .u64 t; cvta.to.shared.u64 t, %1; cvt.u32.u64 %0, t; }" : "=r"(a) : "l"(p));
    return a;
}
#define LDSM4(r, addr) asm volatile( \
    "ldmatrix.sync.aligned.m8n8.x4.shared.b16 {%0,%1,%2,%3}, [%4];" \
    : "=r"((r)[0]), "=r"((r)[1]), "=r"((r)[2]), "=r"((r)[3]) : "r"(addr))
#define MMA(d, a, b0v, b1v) asm volatile( \
    "mma.sync.aligned.m16n8k16.row.col.f32.bf16.bf16.f32 " \
    "{%0,%1,%2,%3}, {%4,%5,%6,%7}, {%8,%9}, {%0,%1,%2,%3};" \
    : "+f"((d)[0]), "+f"((d)[1]), "+f"((d)[2]), "+f"((d)[3]) \
    : "r"((a)[0]), "r"((a)[1]), "r"((a)[2]), "r"((a)[3]), "r"(b0v), "r"(b1v))
__device__ __forceinline__ void cp_async16(uint32_t dst, const void* src) {
    asm volatile("cp.async.cg.shared.global [%0], [%1], 16;" :: "r"(dst), "l"(src));
}
#define CP_COMMIT() asm volatile("cp.async.commit_group;" ::: "memory")
__device__ __forceinline__ void st_release_u32(uint32_t* p, uint32_t v) {
    asm volatile("st.global.release.gpu.b32 [%0], %1;" :: "l"(p), "r"(v) : "memory");
}
__device__ __forceinline__ uint32_t ld_acquire_u32(const uint32_t* p) {
    uint32_t v;
    asm volatile("ld.global.acquire.gpu.b32 %0, [%1];" : "=r"(v) : "l"(p) : "memory");
    return v;
}

// ---------------------------------------------------------------------------
// prep: A fp32 -> hi/lo bf16 (all threads); W split + flag zero.
// W permuted rows: p = nb*256 + branch*128 + (d & 127), nb = d >> 7.
// ---------------------------------------------------------------------------
__global__ void prep_kernel(const float4* __restrict__ A4,
                            const float* __restrict__ W_in,
                            const float* __restrict__ W_f)
{
    int i = blockIdx.x * blockDim.x + threadIdx.x;   // 0 .. 2,097,151
    float4 a = A4[i];
    __nv_bfloat16 h0 = __float2bfloat16_rn(a.x), h1 = __float2bfloat16_rn(a.y),
                  h2 = __float2bfloat16_rn(a.z), h3 = __float2bfloat16_rn(a.w);
    __nv_bfloat162 hp0 = {h0, h1}, hp1 = {h2, h3};
    __nv_bfloat162 lp0 = __floats2bfloat162_rn(a.x - __bfloat162float(h0),
                                               a.y - __bfloat162float(h1));
    __nv_bfloat162 lp1 = __floats2bfloat162_rn(a.z - __bfloat162float(h2),
                                               a.w - __bfloat162float(h3));
    ((uint2*)g_Ahi4)[i] = make_uint2(*(uint32_t*)&hp0, *(uint32_t*)&hp1);
    ((uint2*)g_Alo4)[i] = make_uint2(*(uint32_t*)&lp0, *(uint32_t*)&lp1);

    if (i < NBLK * 128) g_flag[i] = 0u;
    if (i < N_TOT * K_) {
        int p = i >> 8, k = i & 255;
        int nb = p >> 8;
        int rem = p & 255;
        int branch = rem >> 7;
        int d = nb * 128 + (rem & 127);
        float v = branch ? W_f[d * K_ + k] : W_in[d * K_ + k];
        __nv_bfloat16 hi = __float2bfloat16_rn(v);
        ((__nv_bfloat16*)g_Whi4)[i] = hi;
        ((__nv_bfloat16*)g_Wlo4)[i] = __float2bfloat16_rn(v - __bfloat162float(hi));
    }
}

// ---------------------------------------------------------------------------
// Fused: split-bf16 mma GEMM + activations + decoupled-lookback scan + output.
// grid = 512 blocks (256 m-chunks x 2 d-halves), 1024 threads, 1 CTA/SM.
// Block tile: 128 m x 256 n (n_local 0..127 = X cols, 128..255 = F cols).
// 32 warps, each 32 m x 32 n  -> 8 LDSM4 per 24 MMAs (3 MMA/LDSM).
// ---------------------------------------------------------------------------
__global__ __launch_bounds__(1024, 1)
void fused_kernel(const float* __restrict__ b_in,
                  const float* __restrict__ b_f,
                  const float* __restrict__ mask,
                  float* __restrict__ out)
{
    extern __shared__ __align__(16) char smem[];
    const uint32_t sb = smem_u32(smem);
    const int tid = threadIdx.x;
    const int w   = tid >> 5, l = tid & 31;
    const int wm  = w >> 3;           // 0..3, 32-row strip
    const int wn  = w & 7;            // 0..7, 32-col strip
    const int bid = blockIdx.x;
    const int m0  = (bid >> 1) * 128;
    const int hb  = bid & 1;          // d-half

    // issue one stage = A chunk (hi+lo) + W chunk (hi+lo) for k-chunk kc
    auto issueStage = [&](int kc, int buf) {
        const uint32_t base = sb + (buf ? ST_SIZE : 0);
        // A: 128 rows x 8 u4 x 2 arrays = 2048 -> 2 per thread
#pragma unroll
        for (int it = 0; it < 2; it++) {
            int v   = it * 1024 + tid;
            int arr = v >> 10;
            int u   = v & 1023;
            int row = u >> 3, c8 = u & 7;
            uint32_t dst = base + (arr ? ST_ALO : 0)
                         + row * 128 + ((c8 ^ (row & 7)) << 4);
            const uint4* src = (arr ? g_Alo4 : g_Ahi4)
                             + ((size_t)(m0 + row) * 32 + kc * 8 + c8);
            cp_async16(dst, src);
        }
        // W: 256 rows x 8 u4 x 2 arrays = 4096 -> 4 per thread
#pragma unroll
        for (int it = 0; it < 4; it++) {
            int v   = it * 1024 + tid;
            int arr = v >> 11;
            int u   = v & 2047;
            int n   = u >> 3, k8 = u & 7;
            uint32_t dst = base + (arr ? ST_WLO : ST_WHI)
                         + n * 128 + ((k8 ^ (n & 7)) << 4);
            const uint4* src = (arr ? g_Wlo4 : g_Whi4)
                             + ((size_t)(hb * 256 + n) * 32 + kc * 8 + k8);
            cp_async16(dst, src);
        }
        CP_COMMIT();
    };

    issueStage(0, 0);
    issueStage(1, 1);

    // bias / mask staging
    if (tid < 256) {
        int branch = tid >> 7;
        int d = hb * 128 + (tid & 127);
        *(float*)(smem + SM_BIAS + tid * 4) = branch ? b_f[d] : b_in[d];
    }
    if (tid >= 512 && tid < 640) {
        int r = tid - 512;
        *(float*)(smem + SM_MK + r * 4) = mask[m0 + r] * 10000.0f;
    }

    float acc[2][4][4];
#pragma unroll
    for (int a1 = 0; a1 < 2; a1++)
#pragma unroll
        for (int a2 = 0; a2 < 4; a2++)
#pragma unroll
            for (int a3 = 0; a3 < 4; a3++) acc[a1][a2][a3] = 0.0f;

    const int g = l >> 3;

    for (int kc = 0; kc < 4; kc++) {
        const int buf = kc & 1;
        if (kc < 3) asm volatile("cp.async.wait_group 1;" ::: "memory");
        else        asm volatile("cp.async.wait_group 0;" ::: "memory");
        __syncthreads();
        const uint32_t base = sb + (buf ? ST_SIZE : 0);

#pragma unroll
        for (int ks = 0; ks < 4; ks++) {
            const int r0 = wm * 32 + ((g & 1) << 3) + (l & 7);
            const int c  = ks * 16 + ((g & 2) << 2);
            const uint32_t aoff0 = r0 * 128 + ((((c >> 3) ^ (r0 & 7))) << 4);
            uint32_t woff[2];
#pragma unroll
            for (int ng = 0; ng < 2; ng++) {
                int n  = wn * 32 + ng * 16 + ((g & 2) << 2) + (l & 7);
                int kk = ks * 16 + ((g & 1) << 3);
                woff[ng] = n * 128 + ((((kk >> 3) ^ (n & 7))) << 4);
            }

            uint32_t ah[2][4], wb[2][4];
            LDSM4(ah[0], base + aoff0);
            LDSM4(ah[1], base + aoff0 + 16 * 128);
            LDSM4(wb[0], base + ST_WHI + woff[0]);
            LDSM4(wb[1], base + ST_WHI + woff[1]);
            // term hh
#pragma unroll
            for (int mt = 0; mt < 2; mt++)
#pragma unroll
                for (int ng = 0; ng < 2; ng++) {
                    MMA(acc[mt][ng * 2 + 0], ah[mt], wb[ng][0], wb[ng][1]);
                    MMA(acc[mt][ng * 2 + 1], ah[mt], wb[ng][2], wb[ng][3]);
                }
            // term lh
            {
                uint32_t al[2][4];
                LDSM4(al[0], base + ST_ALO + aoff0);
                LDSM4(al[1], base + ST_ALO + aoff0 + 16 * 128);
#pragma unroll
                for (int mt = 0; mt < 2; mt++)
#pragma unroll
                    for (int ng = 0; ng < 2; ng++) {
                        MMA(acc[mt][ng * 2 + 0], al[mt], wb[ng][0], wb[ng][1]);
                        MMA(acc[mt][ng * 2 + 1], al[mt], wb[ng][2], wb[ng][3]);
                    }
            }
            // term hl (reload wb <- W_lo)
            LDSM4(wb[0], base + ST_WLO + woff[0]);
            LDSM4(wb[1], base + ST_WLO + woff[1]);
#pragma unroll
            for (int mt = 0; mt < 2; mt++)
#pragma unroll
                for (int ng = 0; ng < 2; ng++) {
                    MMA(acc[mt][ng * 2 + 0], ah[mt], wb[ng][0], wb[ng][1]);
                    MMA(acc[mt][ng * 2 + 1], ah[mt], wb[ng][2], wb[ng][3]);
                }
        }
        __syncthreads();
        if (kc < 2) issueStage(kc + 2, buf);
    }

    // -------- epilogue: activations -> smem staging --------
    float* xs = (float*)(smem + SM_XS);
    float* fs = (float*)(smem + SM_FS);
    const float* biasS = (const float*)(smem + SM_BIAS);
    const float* mkS   = (const float*)(smem + SM_MK);

#pragma unroll
    for (int mt = 0; mt < 2; mt++)
#pragma unroll
        for (int nt = 0; nt < 4; nt++) {
            int r0 = wm * 32 + mt * 16 + (l >> 2);
            int nl = wn * 32 + nt * 8 + 2 * (l & 3);
            bool isF = (nl >= 128);
            float* stg = isF ? fs : xs;
            int cc = nl & 127;
            float b0 = biasS[nl], b1 = biasS[nl + 1];
#pragma unroll
            for (int h = 0; h < 2; h++) {
                int r = r0 + h * 8;
                float z0 = acc[mt][nt][h * 2 + 0] + b0;
                float z1 = acc[mt][nt][h * 2 + 1] + b1;
                float v0, v1;
                if (isF) {
                    float mk = mkS[r];
                    z0 += mk; z1 += mk;
                    v0 = 1.0f / (1.0f + expf(-z0));
                    v1 = 1.0f / (1.0f + expf(-z1));
                } else {
                    v0 = tanhf(z0);
                    v1 = tanhf(z1);
                }
                stg[r * STG + cc]     = v0;
                stg[r * STG + cc + 1] = v1;
            }
        }
    __syncthreads();

    // -------- lookback scan: 128 threads, one per local channel --------
    if (tid < 128) {
        const int dl = tid;
        const int slot = bid * 128 + dl;

        float hl = 0.0f, Aa = 1.0f;
#pragma unroll 8
        for (int t = 0; t < LCH; t++) {
            float f = fs[t * STG + dl];
            float x = xs[t * STG + dl];
            float om = 1.0f - f;
            hl = fmaf(f, x, om * hl);
            Aa *= om;
        }

        const int c = (bid >> 1) & (NCH - 1);   // chunk index within batch
        float h0 = 0.0f;
        if (c != 0) {
            g_SA [slot] = Aa;
            g_SHl[slot] = hl;
            st_release_u32(&g_flag[slot], 1u);
            float mult = 1.0f;
            int p = slot - 256;                 // (bid-2)*128 + dl
            while (true) {
                uint32_t f;
                do { f = ld_acquire_u32(&g_flag[p]); } while (f == 0u);
                if (f == 2u) { h0 = fmaf(mult, g_SHI[p], h0); break; }
                h0 = fmaf(mult, g_SHl[p], h0);
                mult *= g_SA[p];
                p -= 256;
            }
        }
        g_SHI[slot] = fmaf(Aa, h0, hl);
        st_release_u32(&g_flag[slot], 2u);

        float h = h0;
        float* op = out + (size_t)m0 * D_ + hb * 128 + dl;
#pragma unroll 8
        for (int t = 0; t < LCH; t++) {
            float f = fs[t * STG + dl];
            float x = xs[t * STG + dl];
            h = fmaf(f, x - h, h);
            op[(size_t)t * D_] = h;
        }
    }
}

extern "C" void kernel_launch(void* const* d_in, const int* in_sizes, int n_in,
                              void* d_out, int out_size)
{
    const float* inputs = (const float*)d_in[0];
    const float* mask   = (const float*)d_in[1];
    const float* W_in   = (const float*)d_in[2];
    const float* b_in   = (const float*)d_in[3];
    const float* W_f    = (const float*)d_in[4];
    const float* b_f    = (const float*)d_in[5];
    float* out = (float*)d_out;

    cudaFuncSetAttribute(fused_kernel, cudaFuncAttributeMaxDynamicSharedMemorySize, SM_TOTAL);

    prep_kernel<<<(M_ * K_ / 4) / 256, 256>>>((const float4*)inputs, W_in, W_f);
    fused_kernel<<<NBLK, 1024, SM_TOTAL>>>(b_in, b_f, mask, out);
}